// round 7
// baseline (speedup 1.0000x reference)
#include <cuda_runtime.h>
#include <cuda_bf16.h>
#include <cuda_pipeline.h>
#include <cstdint>

// Problem dims
#define T_DIM 2048
#define B_DIM 16
#define D_DIM 1024
#define N3D   3072          // 3*D
#define MROWS (T_DIM * B_DIM)   // 32768
#define HALF  512
#define EPS   1e-5f

// Chunked scan config
#define NCHUNK 32
#define LOGNC  5
#define CHUNK  64           // T_DIM / NCHUNK

// ---------------- scratch (device globals; no allocations allowed) ------------
__device__ float g_pre[(size_t)MROWS * N3D];                 // ~402 MB (RAW pre-LN)
__device__ float g_s1 [MROWS];                               // per-row sum
__device__ float g_s2 [MROWS];                               // per-row sum of squares
__device__ float g_cA [2 * NCHUNK * B_DIM * HALF];
__device__ float g_cB [2 * NCHUNK * B_DIM * HALF];
__device__ float g_hin[2 * NCHUNK * B_DIM * HALF];

// =============================================================================
// Kernel 0: zero the LN stat accumulators (determinism: every launch).
// =============================================================================
__global__ __launch_bounds__(256) void zero_stats_kernel()
{
    int i = blockIdx.x * 256 + threadIdx.x;
    g_s1[i] = 0.f;
    g_s2[i] = 0.f;
}

// =============================================================================
// Kernel 1: GEMM  pre[M=32768, N=3072] = input[M,1024] @ W[1024,3072]
// tf32 mma.sync m16n8k8, 128x128x32 tiles, 3-stage cp.async, 8 warps,
// warp tile 32x64. Epilogue also accumulates per-row sum / sumsq (atomicAdd).
// =============================================================================
#define BM 128
#define BN 128
#define BK 32
#define KTILES (D_DIM / BK)     // 32
#define STAGES 3
#define LDA_S 36    // bank(addr) = 4g+tg : conflict-free
#define LDB_S 136   // bank = 8tg+g      : conflict-free
#define SA_STAGE (BM * LDA_S)
#define SB_STAGE (BK * LDB_S)
#define SMEM_FLOATS (STAGES * (SA_STAGE + SB_STAGE))
#define SMEM_BYTES  (SMEM_FLOATS * 4)   // 107,520 B

__device__ __forceinline__ void mma_tf32(float* c, const uint32_t* a, const uint32_t* b)
{
    asm volatile(
        "mma.sync.aligned.m16n8k8.row.col.f32.tf32.tf32.f32 "
        "{%0,%1,%2,%3}, {%4,%5,%6,%7}, {%8,%9}, {%0,%1,%2,%3};\n"
        : "+f"(c[0]), "+f"(c[1]), "+f"(c[2]), "+f"(c[3])
        : "r"(a[0]), "r"(a[1]), "r"(a[2]), "r"(a[3]), "r"(b[0]), "r"(b[1]));
}

__device__ __forceinline__ void load_tile_async(
    float* sA, float* sB,
    const float* __restrict__ Ag, const float* __restrict__ Wg,
    int bm, int bn, int k0, int tid)
{
#pragma unroll
    for (int l = 0; l < 4; l++) {
        int e = tid + l * 256;
        int r = e >> 3;
        int c4 = (e & 7) * 4;
        __pipeline_memcpy_async(sA + r * LDA_S + c4,
                                Ag + (size_t)(bm + r) * D_DIM + k0 + c4, 16);
    }
#pragma unroll
    for (int l = 0; l < 4; l++) {
        int e = tid + l * 256;
        int r = e >> 5;
        int c4 = (e & 31) * 4;
        __pipeline_memcpy_async(sB + r * LDB_S + c4,
                                Wg + (size_t)(k0 + r) * N3D + bn + c4, 16);
    }
}

__global__ __launch_bounds__(256, 2) void gemm_tf32_kernel(
    const float* __restrict__ Ag,   // [MROWS, 1024]
    const float* __restrict__ Wg)   // [1024, 3072]
{
    extern __shared__ float smem[];
    float* sAbase = smem;
    float* sBbase = smem + STAGES * SA_STAGE;

    const int tid = threadIdx.x;
    const int bm = blockIdx.y * BM;
    const int bn = blockIdx.x * BN;

    const int warp = tid >> 5;
    const int lane = tid & 31;
    const int wm = warp & 3;
    const int wn = warp >> 2;
    const int g  = lane >> 2;
    const int tg = lane & 3;

    float acc[2][8][4];
#pragma unroll
    for (int mi = 0; mi < 2; mi++)
#pragma unroll
        for (int ni = 0; ni < 8; ni++)
#pragma unroll
            for (int i = 0; i < 4; i++)
                acc[mi][ni][i] = 0.0f;

#pragma unroll
    for (int s = 0; s < STAGES - 1; s++) {
        load_tile_async(sAbase + s * SA_STAGE, sBbase + s * SB_STAGE,
                        Ag, Wg, bm, bn, s * BK, tid);
        __pipeline_commit();
    }

    for (int kt = 0; kt < KTILES; kt++) {
        __pipeline_wait_prior(STAGES - 2);
        __syncthreads();

        int kn = kt + STAGES - 1;
        if (kn < KTILES) {
            int sw = kn % STAGES;
            load_tile_async(sAbase + sw * SA_STAGE, sBbase + sw * SB_STAGE,
                            Ag, Wg, bm, bn, kn * BK, tid);
        }
        __pipeline_commit();

        const float* sA = sAbase + (kt % STAGES) * SA_STAGE;
        const float* sB = sBbase + (kt % STAGES) * SB_STAGE;

        const float* a0p = sA + (wm * 32 + g) * LDA_S + tg;
        const float* b0p = sB + tg * LDB_S + wn * 64 + g;

#pragma unroll
        for (int kk = 0; kk < 4; kk++) {
            const int ko = kk * 8;
            uint32_t af[2][4];
#pragma unroll
            for (int mi = 0; mi < 2; mi++) {
                const float* ap = a0p + mi * 16 * LDA_S + ko;
                af[mi][0] = __float_as_uint(ap[0]);
                af[mi][1] = __float_as_uint(ap[8 * LDA_S]);
                af[mi][2] = __float_as_uint(ap[4]);
                af[mi][3] = __float_as_uint(ap[8 * LDA_S + 4]);
            }
            uint32_t bf[8][2];
#pragma unroll
            for (int ni = 0; ni < 8; ni++) {
                const float* bp = b0p + ko * LDB_S + ni * 8;
                bf[ni][0] = __float_as_uint(bp[0]);
                bf[ni][1] = __float_as_uint(bp[4 * LDB_S]);
            }
#pragma unroll
            for (int mi = 0; mi < 2; mi++)
#pragma unroll
                for (int ni = 0; ni < 8; ni++)
                    mma_tf32(acc[mi][ni], af[mi], bf[ni]);
        }
    }

    // Epilogue: store accumulators + per-row LN stat partials.
#pragma unroll
    for (int mi = 0; mi < 2; mi++) {
        const int r0 = bm + wm * 32 + mi * 16 + g;
        float s1a = 0.f, s2a = 0.f, s1b = 0.f, s2b = 0.f;
#pragma unroll
        for (int ni = 0; ni < 8; ni++) {
            const int col = bn + wn * 64 + ni * 8 + 2 * tg;
            float c0 = acc[mi][ni][0], c1 = acc[mi][ni][1];
            float c2 = acc[mi][ni][2], c3 = acc[mi][ni][3];
            *(float2*)(g_pre + (size_t)r0 * N3D + col)       = make_float2(c0, c1);
            *(float2*)(g_pre + (size_t)(r0 + 8) * N3D + col) = make_float2(c2, c3);
            s1a += c0 + c1;  s2a += c0 * c0 + c1 * c1;
            s1b += c2 + c3;  s2b += c2 * c2 + c3 * c3;
        }
        // reduce over the 4 lanes of the quad (tg = 0..3)
#pragma unroll
        for (int o = 1; o <= 2; o <<= 1) {
            s1a += __shfl_xor_sync(0xffffffffu, s1a, o);
            s2a += __shfl_xor_sync(0xffffffffu, s2a, o);
            s1b += __shfl_xor_sync(0xffffffffu, s1b, o);
            s2b += __shfl_xor_sync(0xffffffffu, s2b, o);
        }
        if (tg == 0) {
            atomicAdd(&g_s1[r0], s1a);
            atomicAdd(&g_s2[r0], s2a);
            atomicAdd(&g_s1[r0 + 8], s1b);
            atomicAdd(&g_s2[r0 + 8], s2b);
        }
    }
}

// =============================================================================
// Inline LN helpers for the scan kernels
// =============================================================================
__device__ __forceinline__ void row_stats(int row, float& mu, float& rsig)
{
    float s1 = __ldg(&g_s1[row]);
    float s2 = __ldg(&g_s2[row]);
    mu = s1 * (1.0f / N3D);
    float var = s2 * (1.0f / N3D) - mu * mu;
    rsig = rsqrtf(var + EPS);
}
__device__ __forceinline__ float ln_val(float raw, float mu, float rsig,
                                        float gm, float bt)
{
    return (raw - mu) * rsig * gm + bt;
}
__device__ __forceinline__ float sigm(float y)
{
    return 1.0f / (1.0f + __expf(-y));
}

// =============================================================================
// Chunked linear recurrence (LN + sigmoid applied inline on raw pre).
// =============================================================================
__device__ __forceinline__ void decode_idx(int idx, int& c, int& b, int& chunk, int& dir) {
    c = idx & (HALF - 1);
    b = (idx >> 9) & (B_DIM - 1);
    chunk = (idx >> 13) & (NCHUNK - 1);
    dir = idx >> (13 + LOGNC);
}

__global__ __launch_bounds__(256) void scan_passA_kernel(
    const float* __restrict__ gamma, const float* __restrict__ beta)
{
    int idx = blockIdx.x * 256 + threadIdx.x;
    int c, b, chunk, dir;
    decode_idx(idx, c, b, chunk, dir);

    const int colg = dir ? (HALF + c) : c;
    const int colx = D_DIM + colg;
    const int t0 = chunk * CHUNK;

    const float gm_g = __ldg(&gamma[colg]), bt_g = __ldg(&beta[colg]);
    const float gm_x = __ldg(&gamma[colx]), bt_x = __ldg(&beta[colx]);

    float A = 1.f, Bv = 0.f;
    if (dir == 0) {
        for (int i = 0; i < CHUNK; i++) {
            int row = (t0 + i) * B_DIM + b;
            float mu, rsig; row_stats(row, mu, rsig);
            size_t base = (size_t)row * N3D;
            float g = sigm(ln_val(g_pre[base + colg], mu, rsig, gm_g, bt_g));
            float x = ln_val(g_pre[base + colx], mu, rsig, gm_x, bt_x);
            float a = 1.f - g;
            Bv = a * Bv + g * x;
            A *= a;
        }
    } else {
        for (int i = CHUNK - 1; i >= 0; i--) {
            int row = (t0 + i) * B_DIM + b;
            float mu, rsig; row_stats(row, mu, rsig);
            size_t base = (size_t)row * N3D;
            float g = sigm(ln_val(g_pre[base + colg], mu, rsig, gm_g, bt_g));
            float x = ln_val(g_pre[base + colx], mu, rsig, gm_x, bt_x);
            float a = 1.f - g;
            Bv = a * Bv + g * x;
            A *= a;
        }
    }
    int off = ((dir * NCHUNK + chunk) * B_DIM + b) * HALF + c;
    g_cA[off] = A;
    g_cB[off] = Bv;
}

__global__ __launch_bounds__(256) void scan_passB_kernel()
{
    int idx = blockIdx.x * 256 + threadIdx.x;
    int c = idx & (HALF - 1);
    int b = (idx >> 9) & (B_DIM - 1);
    int dir = idx >> 13;

    float h = 0.f;
    if (dir == 0) {
        for (int k = 0; k < NCHUNK; k++) {
            int off = ((0 * NCHUNK + k) * B_DIM + b) * HALF + c;
            g_hin[off] = h;
            h = g_cA[off] * h + g_cB[off];
        }
    } else {
        for (int k = NCHUNK - 1; k >= 0; k--) {
            int off = ((1 * NCHUNK + k) * B_DIM + b) * HALF + c;
            g_hin[off] = h;
            h = g_cA[off] * h + g_cB[off];
        }
    }
}

__global__ __launch_bounds__(256) void scan_passC_kernel(
    const float* __restrict__ inp, float* __restrict__ out,
    const float* __restrict__ gamma, const float* __restrict__ beta)
{
    int idx = blockIdx.x * 256 + threadIdx.x;
    int c, b, chunk, dir;
    decode_idx(idx, c, b, chunk, dir);

    const int colg = dir ? (HALF + c) : c;
    const int colx = D_DIM + colg;
    const int colh = 2 * D_DIM + colg;
    const int t0 = chunk * CHUNK;

    const float gm_g = __ldg(&gamma[colg]), bt_g = __ldg(&beta[colg]);
    const float gm_x = __ldg(&gamma[colx]), bt_x = __ldg(&beta[colx]);
    const float gm_h = __ldg(&gamma[colh]), bt_h = __ldg(&beta[colh]);

    float h = g_hin[((dir * NCHUNK + chunk) * B_DIM + b) * HALF + c];

    if (dir == 0) {
        for (int i = 0; i < CHUNK; i++) {
            int row = (t0 + i) * B_DIM + b;
            float mu, rsig; row_stats(row, mu, rsig);
            size_t base = (size_t)row * N3D;
            float g = sigm(ln_val(g_pre[base + colg], mu, rsig, gm_g, bt_g));
            float x = ln_val(g_pre[base + colx], mu, rsig, gm_x, bt_x);
            h = (1.f - g) * h + g * x;
            float hg = sigm(ln_val(g_pre[base + colh], mu, rsig, gm_h, bt_h));
            size_t ib = (size_t)row * D_DIM + colg;
            out[ib] = h + hg * (inp[ib] - h);
        }
    } else {
        for (int i = CHUNK - 1; i >= 0; i--) {
            int row = (t0 + i) * B_DIM + b;
            float mu, rsig; row_stats(row, mu, rsig);
            size_t base = (size_t)row * N3D;
            float g = sigm(ln_val(g_pre[base + colg], mu, rsig, gm_g, bt_g));
            float x = ln_val(g_pre[base + colx], mu, rsig, gm_x, bt_x);
            h = (1.f - g) * h + g * x;
            float hg = sigm(ln_val(g_pre[base + colh], mu, rsig, gm_h, bt_h));
            size_t ib = (size_t)row * D_DIM + colg;
            out[ib] = h + hg * (inp[ib] - h);
        }
    }
}

// =============================================================================
extern "C" void kernel_launch(void* const* d_in, const int* in_sizes, int n_in,
                              void* d_out, int out_size)
{
    const float* inp   = (const float*)d_in[0];   // (T,B,D)
    const float* W     = (const float*)d_in[1];   // (D, 3D)
    const float* gamma = (const float*)d_in[2];   // (3D,)
    const float* beta  = (const float*)d_in[3];   // (3D,)
    float* out = (float*)d_out;

    static bool attr_set = false;
    if (!attr_set) {
        cudaFuncSetAttribute(gemm_tf32_kernel,
                             cudaFuncAttributeMaxDynamicSharedMemorySize, SMEM_BYTES);
        attr_set = true;
    }

    zero_stats_kernel<<<MROWS / 256, 256>>>();

    dim3 ggrid(N3D / BN, MROWS / BM);             // 24 x 256
    gemm_tf32_kernel<<<ggrid, 256, SMEM_BYTES>>>(inp, W);

    scan_passA_kernel<<<(2 * NCHUNK * B_DIM * HALF) / 256, 256>>>(gamma, beta);
    scan_passB_kernel<<<(2 * B_DIM * HALF) / 256, 256>>>();
    scan_passC_kernel<<<(2 * NCHUNK * B_DIM * HALF) / 256, 256>>>(inp, out, gamma, beta);
}